// round 5
// baseline (speedup 1.0000x reference)
#include <cuda_runtime.h>

#define D 128
#define MAX_N 50000
#define MAX_E 500000
#define EPB 16
#define NPB 16

// ---------------- scratch (no allocation allowed) ----------------
__device__ float g_agg_h[(size_t)MAX_N * D];   // segment_sum(edge_feat, row)
__device__ float g_agg_c[MAX_N * 3];           // segment_sum(trans, row)
__device__ float g_cnt[MAX_N];                 // per-row edge count
__device__ int   g_idx64;                      // 1 if edge_index is int64

// ---------------- helpers ----------------
__device__ __forceinline__ float siluf(float x) {
    return x / (1.0f + __expf(-x));
}
__device__ __forceinline__ float sigm(float x) {
    return 1.0f / (1.0f + __expf(-x));
}
__device__ __forceinline__ float wsum(float v) {
    v += __shfl_xor_sync(0xffffffffu, v, 16);
    v += __shfl_xor_sync(0xffffffffu, v, 8);
    v += __shfl_xor_sync(0xffffffffu, v, 4);
    v += __shfl_xor_sync(0xffffffffu, v, 2);
    v += __shfl_xor_sync(0xffffffffu, v, 1);
    return v;
}

// Detect whether edge_index is int64 (high words all zero) or int32.
__global__ void detect_kernel(const int* __restrict__ ei) {
    if (threadIdx.x == 0) {
        int nz = 0;
        for (int i = 1; i < 128; i += 2) nz |= ei[i];
        g_idx64 = (nz == 0) ? 1 : 0;
    }
}

__global__ void zero_kernel(int N) {
    long tot = (long)N * D + (long)N * 3 + N;
    long stride = (long)gridDim.x * blockDim.x;
    for (long i = (long)blockIdx.x * blockDim.x + threadIdx.x; i < tot; i += stride) {
        if (i < (long)N * D)               g_agg_h[i] = 0.0f;
        else if (i < (long)N * D + 3L * N) g_agg_c[i - (long)N * D] = 0.0f;
        else                               g_cnt[i - (long)N * D - 3L * N] = 0.0f;
    }
}

// ---------------- fused edge kernel ----------------
// 128 threads, EPB edges per block. Thread t owns output feature t.
__global__ __launch_bounds__(128) void edge_kernel(
    const float* __restrict__ h, const void* __restrict__ eiv,
    const float* __restrict__ coord,
    const float* __restrict__ We1, const float* __restrict__ be1,
    const float* __restrict__ We2, const float* __restrict__ be2,
    const float* __restrict__ Watt, const float* __restrict__ batt,
    const float* __restrict__ Wc1, const float* __restrict__ bc1,
    const float* __restrict__ Wc2,
    float* __restrict__ out_ef, int E)
{
    __shared__ __align__(16) float in_s[EPB][264];   // [0,128) h_row, [128,256) h_col, [256] radial
    __shared__ __align__(16) float hid_s[EPB][128];  // edge_mlp layer-1 output
    __shared__ __align__(16) float mij_s[EPB][128];  // edge_mlp layer-2 output (pre-attention)
    __shared__ float red_s[4][EPB];
    __shared__ float att_s[EPB];
    __shared__ float cw_s[EPB];
    __shared__ float cd_s[EPB][3];
    __shared__ int   row_s[EPB], col_s[EPB];

    const int t = threadIdx.x;
    const int lane = t & 31;
    const int warp = t >> 5;
    const long e0 = (long)blockIdx.x * EPB;
    const int idx64 = g_idx64;

    // edge indices
    if (t < EPB) {
        long e = e0 + t;
        int r = 0, c = 0;
        if (e < E) {
            if (idx64) {
                const long long* ei = (const long long*)eiv;
                r = (int)ei[e];
                c = (int)ei[(long)E + e];
            } else {
                const int* ei = (const int*)eiv;
                r = ei[e];
                c = ei[(long)E + e];
            }
        }
        row_s[t] = r;
        col_s[t] = c;
    }
    __syncthreads();

    // gather h rows (coalesced; h is L2-resident) + coord diff
#pragma unroll
    for (int e = 0; e < EPB; e++) {
        in_s[e][t]       = h[(long)row_s[e] * D + t];
        in_s[e][128 + t] = h[(long)col_s[e] * D + t];
    }
    if (t < EPB * 3) {
        int e = t / 3, d = t % 3;
        cd_s[e][d] = coord[(long)row_s[e] * 3 + d] - coord[(long)col_s[e] * 3 + d];
    }
    __syncthreads();
    if (t < EPB) {
        float x = cd_s[t][0], y = cd_s[t][1], z = cd_s[t][2];
        in_s[t][256] = x * x + y * y + z * z;   // radial
    }
    __syncthreads();

    float acc[EPB];

    // ---- edge_mlp layer 1: [2D+1] -> D, SiLU ----
#pragma unroll
    for (int e = 0; e < EPB; e++) acc[e] = 0.0f;
#pragma unroll 2
    for (int k = 0; k < 256; k += 4) {
        float w0 = We1[(k + 0) * D + t];
        float w1 = We1[(k + 1) * D + t];
        float w2 = We1[(k + 2) * D + t];
        float w3 = We1[(k + 3) * D + t];
#pragma unroll
        for (int e = 0; e < EPB; e++) {
            float4 v = *(const float4*)&in_s[e][k];
            acc[e] = fmaf(v.x, w0, fmaf(v.y, w1, fmaf(v.z, w2, fmaf(v.w, w3, acc[e]))));
        }
    }
    {
        float wr = We1[256 * D + t];
        float b  = be1[t];
#pragma unroll
        for (int e = 0; e < EPB; e++) {
            float x = fmaf(in_s[e][256], wr, acc[e] + b);
            hid_s[e][t] = siluf(x);
        }
    }
    __syncthreads();

    // ---- edge_mlp layer 2: D -> D, SiLU ----
#pragma unroll
    for (int e = 0; e < EPB; e++) acc[e] = 0.0f;
#pragma unroll 2
    for (int k = 0; k < 128; k += 4) {
        float w0 = We2[(k + 0) * D + t];
        float w1 = We2[(k + 1) * D + t];
        float w2 = We2[(k + 2) * D + t];
        float w3 = We2[(k + 3) * D + t];
#pragma unroll
        for (int e = 0; e < EPB; e++) {
            float4 v = *(const float4*)&hid_s[e][k];
            acc[e] = fmaf(v.x, w0, fmaf(v.y, w1, fmaf(v.z, w2, fmaf(v.w, w3, acc[e]))));
        }
    }
    {
        float b = be2[t];
#pragma unroll
        for (int e = 0; e < EPB; e++) {
            float m = siluf(acc[e] + b);
            mij_s[e][t] = m;
            acc[e] = m;                // keep mij in regs for att + edge_feat
        }
    }

    // ---- attention: sigmoid(mij @ Watt + batt) ----
    {
        float wa = Watt[t];
#pragma unroll
        for (int e = 0; e < EPB; e++) {
            float r = wsum(acc[e] * wa);
            if (lane == 0) red_s[warp][e] = r;
        }
    }
    __syncthreads();
    if (t < EPB) {
        float s = red_s[0][t] + red_s[1][t] + red_s[2][t] + red_s[3][t] + batt[0];
        att_s[t] = sigm(s);
    }
    __syncthreads();

    // ---- edge_feat = mij * att : write output + scatter-sum into agg_h ----
#pragma unroll
    for (int e = 0; e < EPB; e++) {
        long eg = e0 + e;
        if (eg < E) {
            float ef = acc[e] * att_s[e];
            out_ef[eg * D + t] = ef;
            atomicAdd(&g_agg_h[(long)row_s[e] * D + t], ef);
        }
    }

    // ---- coord_mlp: cw = silu(edge_feat @ Wc1 + bc1) @ Wc2 ----
    // edge_feat = att * mij, so dot(edge_feat, Wc1col) = att * dot(mij, Wc1col)
#pragma unroll
    for (int e = 0; e < EPB; e++) acc[e] = 0.0f;
#pragma unroll 2
    for (int k = 0; k < 128; k += 4) {
        float w0 = Wc1[(k + 0) * D + t];
        float w1 = Wc1[(k + 1) * D + t];
        float w2 = Wc1[(k + 2) * D + t];
        float w3 = Wc1[(k + 3) * D + t];
#pragma unroll
        for (int e = 0; e < EPB; e++) {
            float4 v = *(const float4*)&mij_s[e][k];
            acc[e] = fmaf(v.x, w0, fmaf(v.y, w1, fmaf(v.z, w2, fmaf(v.w, w3, acc[e]))));
        }
    }
    {
        float bc  = bc1[t];
        float wc2 = Wc2[t];
#pragma unroll
        for (int e = 0; e < EPB; e++) {
            float pre = fmaf(att_s[e], acc[e], bc);
            float r = wsum(siluf(pre) * wc2);
            if (lane == 0) red_s[warp][e] = r;
        }
    }
    __syncthreads();
    if (t < EPB)
        cw_s[t] = red_s[0][t] + red_s[1][t] + red_s[2][t] + red_s[3][t];
    __syncthreads();

    // ---- trans = clip(coord_diff * cw, +/-10); scatter into agg_c, cnt ----
    if (t < EPB * 3) {
        int e = t / 3, d = t % 3;
        long eg = e0 + e;
        if (eg < E) {
            float tr = cd_s[e][d] * cw_s[e];
            tr = fminf(10.0f, fmaxf(-10.0f, tr));
            atomicAdd(&g_agg_c[(long)row_s[e] * 3 + d], tr);
        }
    }
    if (t < EPB) {
        long eg = e0 + t;
        if (eg < E) atomicAdd(&g_cnt[row_s[t]], 1.0f);
    }
}

// ---------------- node kernel: h_out = h + node_mlp([h, agg]) ----------------
__global__ __launch_bounds__(128) void node_kernel(
    const float* __restrict__ h,
    const float* __restrict__ Wn1, const float* __restrict__ bn1,
    const float* __restrict__ Wn2, const float* __restrict__ bn2,
    float* __restrict__ h_out, int N)
{
    __shared__ __align__(16) float in_s[NPB][256];
    __shared__ __align__(16) float hid_s[NPB][128];

    const int t = threadIdx.x;
    const long n0 = (long)blockIdx.x * NPB;

#pragma unroll
    for (int e = 0; e < NPB; e++) {
        long n = n0 + e;
        if (n >= N) n = N - 1;
        in_s[e][t]       = h[n * D + t];
        in_s[e][128 + t] = g_agg_h[n * D + t];
    }
    __syncthreads();

    float acc[NPB];
#pragma unroll
    for (int e = 0; e < NPB; e++) acc[e] = 0.0f;
#pragma unroll 2
    for (int k = 0; k < 256; k += 4) {
        float w0 = Wn1[(k + 0) * D + t];
        float w1 = Wn1[(k + 1) * D + t];
        float w2 = Wn1[(k + 2) * D + t];
        float w3 = Wn1[(k + 3) * D + t];
#pragma unroll
        for (int e = 0; e < NPB; e++) {
            float4 v = *(const float4*)&in_s[e][k];
            acc[e] = fmaf(v.x, w0, fmaf(v.y, w1, fmaf(v.z, w2, fmaf(v.w, w3, acc[e]))));
        }
    }
    {
        float b = bn1[t];
#pragma unroll
        for (int e = 0; e < NPB; e++) hid_s[e][t] = siluf(acc[e] + b);
    }
    __syncthreads();

#pragma unroll
    for (int e = 0; e < NPB; e++) acc[e] = 0.0f;
#pragma unroll 2
    for (int k = 0; k < 128; k += 4) {
        float w0 = Wn2[(k + 0) * D + t];
        float w1 = Wn2[(k + 1) * D + t];
        float w2 = Wn2[(k + 2) * D + t];
        float w3 = Wn2[(k + 3) * D + t];
#pragma unroll
        for (int e = 0; e < NPB; e++) {
            float4 v = *(const float4*)&hid_s[e][k];
            acc[e] = fmaf(v.x, w0, fmaf(v.y, w1, fmaf(v.z, w2, fmaf(v.w, w3, acc[e]))));
        }
    }
    {
        float b2 = bn2[t];
#pragma unroll
        for (int e = 0; e < NPB; e++) {
            long n = n0 + e;
            if (n < N) h_out[n * D + t] = in_s[e][t] + acc[e] + b2;  // residual
        }
    }
}

// ---------------- coord finalize: coord + clip(agg_c / max(cnt,1), +/-10) ----
__global__ void coord_kernel(const float* __restrict__ coord,
                             float* __restrict__ coord_out, int N)
{
    int i = blockIdx.x * blockDim.x + threadIdx.x;
    if (i < N * 3) {
        int n = i / 3;
        float m = g_agg_c[i] / fmaxf(g_cnt[n], 1.0f);
        m = fminf(10.0f, fmaxf(-10.0f, m));
        coord_out[i] = coord[i] + m;
    }
}

// ---------------- launch ----------------
extern "C" void kernel_launch(void* const* d_in, const int* in_sizes, int n_in,
                              void* d_out, int out_size)
{
    const float* h     = (const float*)d_in[0];
    const void*  ei    = d_in[1];
    const float* coord = (const float*)d_in[2];
    const float* We1   = (const float*)d_in[3];
    const float* be1   = (const float*)d_in[4];
    const float* We2   = (const float*)d_in[5];
    const float* be2   = (const float*)d_in[6];
    const float* Watt  = (const float*)d_in[7];
    const float* batt  = (const float*)d_in[8];
    const float* Wc1   = (const float*)d_in[9];
    const float* bc1   = (const float*)d_in[10];
    const float* Wc2   = (const float*)d_in[11];
    const float* Wn1   = (const float*)d_in[12];
    const float* bn1   = (const float*)d_in[13];
    const float* Wn2   = (const float*)d_in[14];
    const float* bn2   = (const float*)d_in[15];

    const int N = in_sizes[0] / D;
    const int E = in_sizes[1] / 2;

    float* out       = (float*)d_out;
    float* h_out     = out;
    float* coord_out = out + (long)N * D;
    float* out_ef    = out + (long)N * D + (long)N * 3;

    detect_kernel<<<1, 32>>>((const int*)ei);
    zero_kernel<<<1024, 256>>>(N);

    int eb = (E + EPB - 1) / EPB;
    edge_kernel<<<eb, 128>>>(h, ei, coord,
                             We1, be1, We2, be2, Watt, batt,
                             Wc1, bc1, Wc2, out_ef, E);

    int nb = (N + NPB - 1) / NPB;
    node_kernel<<<nb, 128>>>(h, Wn1, bn1, Wn2, bn2, h_out, N);

    coord_kernel<<<(N * 3 + 255) / 256, 256>>>(coord, coord_out, N);
}

// round 7
// speedup vs baseline: 1.0919x; 1.0919x over previous
#include <cuda_runtime.h>
#include <stdint.h>

#define D 128
#define MAX_N 50000
#define MAX_E 500000
#define EPB 16
#define NPB 16
#define RS 20   // padded row stride (floats) for transposed smem tiles; 80B keeps 16B alignment

// ---------------- scratch (no allocation allowed) ----------------
__device__ float g_agg_h[(size_t)MAX_N * D];   // segment_sum(edge_feat, row)
__device__ float g_agg_c[MAX_N * 3];           // segment_sum(trans, row)
__device__ float g_cnt[MAX_N];                 // per-row edge count
__device__ int   g_idx64;                      // 1 if edge_index is int64

typedef unsigned long long ull;

// ---------------- packed f32x2 helpers ----------------
#define PACK2(d, lo, hi)  asm("mov.b64 %0, {%1, %2};" : "=l"(d) : "r"(lo), "r"(hi))
#define UNPACK2(lo, hi, s) asm("mov.b64 {%0, %1}, %2;" : "=r"(lo), "=r"(hi) : "l"(s))
#define FMA2(d, a, b, c)  asm("fma.rn.f32x2 %0, %1, %2, %3;" : "=l"(d) : "l"(a), "l"(b), "l"(c))
#define ADD2(d, a, b)     asm("add.rn.f32x2 %0, %1, %2;" : "=l"(d) : "l"(a), "l"(b))

__device__ __forceinline__ float siluf(float x) { return x / (1.0f + __expf(-x)); }
__device__ __forceinline__ float sigm(float x)  { return 1.0f / (1.0f + __expf(-x)); }

__device__ __forceinline__ ull dup2(float x) {
    ull r; uint32_t u = __float_as_uint(x);
    PACK2(r, u, u);
    return r;
}
__device__ __forceinline__ ull silu2(ull x) {
    uint32_t a, b; UNPACK2(a, b, x);
    uint32_t u0 = __float_as_uint(siluf(__uint_as_float(a)));
    uint32_t u1 = __float_as_uint(siluf(__uint_as_float(b)));
    ull r; PACK2(r, u0, u1);
    return r;
}
__device__ __forceinline__ void st2(float* p, ull x) {
    uint32_t a, b; UNPACK2(a, b, x);
    *(float2*)p = make_float2(__uint_as_float(a), __uint_as_float(b));
}
__device__ __forceinline__ float lo2(ull x) { uint32_t a, b; UNPACK2(a, b, x); return __uint_as_float(a); }
__device__ __forceinline__ float hi2(ull x) { uint32_t a, b; UNPACK2(a, b, x); return __uint_as_float(b); }

__device__ __forceinline__ float wsum(float v) {
    v += __shfl_xor_sync(0xffffffffu, v, 16);
    v += __shfl_xor_sync(0xffffffffu, v, 8);
    v += __shfl_xor_sync(0xffffffffu, v, 4);
    v += __shfl_xor_sync(0xffffffffu, v, 2);
    v += __shfl_xor_sync(0xffffffffu, v, 1);
    return v;
}

// rank-1-per-k outer product: acc pairs over 16 edges, feature t per thread.
// in is [K][RS] transposed (k-major), W is [K][D] row-major.
template<int K>
__device__ __forceinline__ void mm_pairs(const float (*__restrict__ in)[RS],
                                         const float* __restrict__ W,
                                         int t, ull acc[8]) {
#pragma unroll 4
    for (int k = 0; k < K; k++) {
        ull w = dup2(W[k * D + t]);
#pragma unroll
        for (int j = 0; j < 4; j++) {
            ulonglong2 u = *(const ulonglong2*)&in[k][4 * j];
            FMA2(acc[2 * j],     w, u.x, acc[2 * j]);
            FMA2(acc[2 * j + 1], w, u.y, acc[2 * j + 1]);
        }
    }
}

// Detect whether edge_index is int64 (high words all zero) or int32.
__global__ void detect_kernel(const int* __restrict__ ei) {
    if (threadIdx.x == 0) {
        int nz = 0;
        for (int i = 1; i < 128; i += 2) nz |= ei[i];
        g_idx64 = (nz == 0) ? 1 : 0;
    }
}

__global__ void zero_kernel(int N) {
    long tot = (long)N * D + (long)N * 3 + N;
    long stride = (long)gridDim.x * blockDim.x;
    for (long i = (long)blockIdx.x * blockDim.x + threadIdx.x; i < tot; i += stride) {
        if (i < (long)N * D)               g_agg_h[i] = 0.0f;
        else if (i < (long)N * D + 3L * N) g_agg_c[i - (long)N * D] = 0.0f;
        else                               g_cnt[i - (long)N * D - 3L * N] = 0.0f;
    }
}

// ---------------- fused edge kernel ----------------
// 128 threads; thread t owns output feature t; 16 edges/block packed as 8 f32x2 pairs.
__global__ __launch_bounds__(128) void edge_kernel(
    const float* __restrict__ h, const void* __restrict__ eiv,
    const float* __restrict__ coord,
    const float* __restrict__ We1, const float* __restrict__ be1,
    const float* __restrict__ We2, const float* __restrict__ be2,
    const float* __restrict__ Watt, const float* __restrict__ batt,
    const float* __restrict__ Wc1, const float* __restrict__ bc1,
    const float* __restrict__ Wc2,
    float* __restrict__ out_ef, int E)
{
    __shared__ __align__(16) float in_t[257][RS];   // [k][e]: 0-127 h_row, 128-255 h_col, 256 radial
    __shared__ __align__(16) float hid_t[128][RS];  // layer-1 output, transposed
    __shared__ __align__(16) float mij_t[128][RS];  // layer-2 output (pre-attention), transposed
    __shared__ float red_s[4][EPB];
    __shared__ float att_s[EPB];
    __shared__ float cw_s[EPB];
    __shared__ float cd_s[EPB][3];
    __shared__ int   row_s[EPB], col_s[EPB];

    const int t = threadIdx.x;
    const int lane = t & 31;
    const int warp = t >> 5;
    const long e0 = (long)blockIdx.x * EPB;
    const int idx64 = g_idx64;

    // edge indices
    if (t < EPB) {
        long e = e0 + t;
        int r = 0, c = 0;
        if (e < E) {
            if (idx64) {
                const long long* ei = (const long long*)eiv;
                r = (int)ei[e];
                c = (int)ei[(long)E + e];
            } else {
                const int* ei = (const int*)eiv;
                r = ei[e];
                c = ei[(long)E + e];
            }
        }
        row_s[t] = r;
        col_s[t] = c;
    }
    __syncthreads();

    // gather h rows into transposed tile (coalesced LDG; 4-way STS conflicts only)
#pragma unroll
    for (int e = 0; e < EPB; e++) {
        in_t[t][e]       = h[(long)row_s[e] * D + t];
        in_t[128 + t][e] = h[(long)col_s[e] * D + t];
    }
    if (t < EPB * 3) {
        int e = t / 3, d = t % 3;
        cd_s[e][d] = coord[(long)row_s[e] * 3 + d] - coord[(long)col_s[e] * 3 + d];
    }
    __syncthreads();
    if (t < EPB) {
        float x = cd_s[t][0], y = cd_s[t][1], z = cd_s[t][2];
        in_t[256][t] = x * x + y * y + z * z;   // radial
    }
    __syncthreads();

    ull acc[8];

    // ---- edge_mlp layer 1: [2D+1] -> D, SiLU ----
#pragma unroll
    for (int j = 0; j < 8; j++) acc[j] = 0ull;
    mm_pairs<257>(in_t, We1, t, acc);
    {
        ull b = dup2(be1[t]);
#pragma unroll
        for (int j = 0; j < 8; j++) {
            ADD2(acc[j], acc[j], b);
            acc[j] = silu2(acc[j]);
            st2(&hid_t[t][2 * j], acc[j]);
        }
    }
    __syncthreads();

    // ---- edge_mlp layer 2: D -> D, SiLU ----
#pragma unroll
    for (int j = 0; j < 8; j++) acc[j] = 0ull;
    mm_pairs<128>(hid_t, We2, t, acc);
    float m[EPB];
    {
        ull b = dup2(be2[t]);
#pragma unroll
        for (int j = 0; j < 8; j++) {
            ADD2(acc[j], acc[j], b);
            acc[j] = silu2(acc[j]);
            st2(&mij_t[t][2 * j], acc[j]);
            m[2 * j]     = lo2(acc[j]);
            m[2 * j + 1] = hi2(acc[j]);
        }
    }

    // ---- attention: sigmoid(mij @ Watt + batt) ----
    {
        float wa = Watt[t];
#pragma unroll
        for (int e = 0; e < EPB; e++) {
            float r = wsum(m[e] * wa);
            if (lane == 0) red_s[warp][e] = r;
        }
    }
    __syncthreads();   // also publishes mij_t for the coord layer
    if (t < EPB) {
        float s = red_s[0][t] + red_s[1][t] + red_s[2][t] + red_s[3][t] + batt[0];
        att_s[t] = sigm(s);
    }
    __syncthreads();

    // ---- edge_feat = mij * att : write output + scatter-sum into agg_h ----
#pragma unroll
    for (int e = 0; e < EPB; e++) {
        long eg = e0 + e;
        if (eg < E) {
            float ef = m[e] * att_s[e];
            out_ef[eg * D + t] = ef;
            atomicAdd(&g_agg_h[(long)row_s[e] * D + t], ef);
        }
    }

    // ---- coord_mlp: cw = silu(edge_feat @ Wc1 + bc1) @ Wc2 ----
    // edge_feat = att * mij, so dot(edge_feat, Wc1col) = att * dot(mij, Wc1col)
#pragma unroll
    for (int j = 0; j < 8; j++) acc[j] = 0ull;
    mm_pairs<128>(mij_t, Wc1, t, acc);
    {
        float bc  = bc1[t];
        float wc2 = Wc2[t];
#pragma unroll
        for (int j = 0; j < 8; j++) {
            float a0 = lo2(acc[j]), a1 = hi2(acc[j]);
            float p0 = fmaf(att_s[2 * j],     a0, bc);
            float p1 = fmaf(att_s[2 * j + 1], a1, bc);
            float r0 = wsum(siluf(p0) * wc2);
            float r1 = wsum(siluf(p1) * wc2);
            if (lane == 0) { red_s[warp][2 * j] = r0; red_s[warp][2 * j + 1] = r1; }
        }
    }
    __syncthreads();
    if (t < EPB)
        cw_s[t] = red_s[0][t] + red_s[1][t] + red_s[2][t] + red_s[3][t];
    __syncthreads();

    // ---- trans = clip(coord_diff * cw, +/-10); scatter into agg_c, cnt ----
    if (t < EPB * 3) {
        int e = t / 3, d = t % 3;
        long eg = e0 + e;
        if (eg < E) {
            float tr = cd_s[e][d] * cw_s[e];
            tr = fminf(10.0f, fmaxf(-10.0f, tr));
            atomicAdd(&g_agg_c[(long)row_s[e] * 3 + d], tr);
        }
    }
    if (t < EPB) {
        long eg = e0 + t;
        if (eg < E) atomicAdd(&g_cnt[row_s[t]], 1.0f);
    }
}

// ---------------- node kernel: h_out = h + node_mlp([h, agg]) ----------------
__global__ __launch_bounds__(128) void node_kernel(
    const float* __restrict__ h,
    const float* __restrict__ Wn1, const float* __restrict__ bn1,
    const float* __restrict__ Wn2, const float* __restrict__ bn2,
    float* __restrict__ h_out, int N)
{
    __shared__ __align__(16) float in_t[256][RS];
    __shared__ __align__(16) float hid_t[128][RS];

    const int t = threadIdx.x;
    const long n0 = (long)blockIdx.x * NPB;

#pragma unroll
    for (int e = 0; e < NPB; e++) {
        long n = n0 + e;
        if (n >= N) n = N - 1;
        in_t[t][e]       = h[n * D + t];
        in_t[128 + t][e] = g_agg_h[n * D + t];
    }
    __syncthreads();

    ull acc[8];
#pragma unroll
    for (int j = 0; j < 8; j++) acc[j] = 0ull;
    mm_pairs<256>(in_t, Wn1, t, acc);
    {
        ull b = dup2(bn1[t]);
#pragma unroll
        for (int j = 0; j < 8; j++) {
            ADD2(acc[j], acc[j], b);
            st2(&hid_t[t][2 * j], silu2(acc[j]));
        }
    }
    __syncthreads();

#pragma unroll
    for (int j = 0; j < 8; j++) acc[j] = 0ull;
    mm_pairs<128>(hid_t, Wn2, t, acc);
    {
        float b2 = bn2[t];
#pragma unroll
        for (int j = 0; j < 8; j++) {
            float a0 = lo2(acc[j]), a1 = hi2(acc[j]);
            long n = n0 + 2 * j;
            if (n < N)     h_out[n * D + t]       = in_t[t][2 * j]     + a0 + b2;  // residual
            if (n + 1 < N) h_out[(n + 1) * D + t] = in_t[t][2 * j + 1] + a1 + b2;
        }
    }
}

// ---------------- coord finalize: coord + clip(agg_c / max(cnt,1), +/-10) ----
__global__ void coord_kernel(const float* __restrict__ coord,
                             float* __restrict__ coord_out, int N)
{
    int i = blockIdx.x * blockDim.x + threadIdx.x;
    if (i < N * 3) {
        int n = i / 3;
        float m = g_agg_c[i] / fmaxf(g_cnt[n], 1.0f);
        m = fminf(10.0f, fmaxf(-10.0f, m));
        coord_out[i] = coord[i] + m;
    }
}

// ---------------- launch ----------------
extern "C" void kernel_launch(void* const* d_in, const int* in_sizes, int n_in,
                              void* d_out, int out_size)
{
    const float* h     = (const float*)d_in[0];
    const void*  ei    = d_in[1];
    const float* coord = (const float*)d_in[2];
    const float* We1   = (const float*)d_in[3];
    const float* be1   = (const float*)d_in[4];
    const float* We2   = (const float*)d_in[5];
    const float* be2   = (const float*)d_in[6];
    const float* Watt  = (const float*)d_in[7];
    const float* batt  = (const float*)d_in[8];
    const float* Wc1   = (const float*)d_in[9];
    const float* bc1   = (const float*)d_in[10];
    const float* Wc2   = (const float*)d_in[11];
    const float* Wn1   = (const float*)d_in[12];
    const float* bn1   = (const float*)d_in[13];
    const float* Wn2   = (const float*)d_in[14];
    const float* bn2   = (const float*)d_in[15];

    const int N = in_sizes[0] / D;
    const int E = in_sizes[1] / 2;

    float* out       = (float*)d_out;
    float* h_out     = out;
    float* coord_out = out + (long)N * D;
    float* out_ef    = out + (long)N * D + (long)N * 3;

    detect_kernel<<<1, 32>>>((const int*)ei);
    zero_kernel<<<1024, 256>>>(N);

    int eb = (E + EPB - 1) / EPB;
    edge_kernel<<<eb, 128>>>(h, ei, coord,
                             We1, be1, We2, be2, Watt, batt,
                             Wc1, bc1, Wc2, out_ef, E);

    int nb = (N + NPB - 1) / NPB;
    node_kernel<<<nb, 128>>>(h, Wn1, bn1, Wn2, bn2, h_out, N);

    coord_kernel<<<(N * 3 + 255) / 256, 256>>>(coord, coord_out, N);
}

// round 8
// speedup vs baseline: 1.1620x; 1.0642x over previous
#include <cuda_runtime.h>
#include <stdint.h>

#define D 128
#define MAX_N 50000
#define MAX_E 500000
#define EPB 16
#define RS 20   // padded row stride (floats); multiple of 4 keeps LDS.128 alignment

// ---------------- scratch (no allocation allowed) ----------------
__device__ float g_agg_h[(size_t)MAX_N * D];   // segment_sum(edge_feat, row)
__device__ float g_agg_c[MAX_N * 3];           // segment_sum(trans, row)
__device__ float g_cnt[MAX_N];                 // per-row edge count
__device__ int   g_idx64;                      // 1 if edge_index is int64

typedef unsigned long long ull;

// ---------------- packed f32x2 helpers ----------------
#define PACK2(d, lo, hi)   asm("mov.b64 %0, {%1, %2};" : "=l"(d) : "r"(lo), "r"(hi))
#define UNPACK2(lo, hi, s) asm("mov.b64 {%0, %1}, %2;" : "=r"(lo), "=r"(hi) : "l"(s))
#define FMA2(d, a, b, c)   asm("fma.rn.f32x2 %0, %1, %2, %3;" : "=l"(d) : "l"(a), "l"(b), "l"(c))
#define ADD2(d, a, b)      asm("add.rn.f32x2 %0, %1, %2;" : "=l"(d) : "l"(a), "l"(b))
#define MUL2(d, a, b)      asm("mul.rn.f32x2 %0, %1, %2;" : "=l"(d) : "l"(a), "l"(b))

__device__ __forceinline__ float siluf(float x) { return x / (1.0f + __expf(-x)); }
__device__ __forceinline__ float sigm(float x)  { return 1.0f / (1.0f + __expf(-x)); }

__device__ __forceinline__ ull dup2(float x) {
    ull r; uint32_t u = __float_as_uint(x);
    PACK2(r, u, u);
    return r;
}
__device__ __forceinline__ ull pack2f(float a, float b) {
    ull r; PACK2(r, __float_as_uint(a), __float_as_uint(b));
    return r;
}
__device__ __forceinline__ ull silu2(ull x) {
    uint32_t a, b; UNPACK2(a, b, x);
    uint32_t u0 = __float_as_uint(siluf(__uint_as_float(a)));
    uint32_t u1 = __float_as_uint(siluf(__uint_as_float(b)));
    ull r; PACK2(r, u0, u1);
    return r;
}
__device__ __forceinline__ void st2(float* p, ull x) {
    uint32_t a, b; UNPACK2(a, b, x);
    *(float2*)p = make_float2(__uint_as_float(a), __uint_as_float(b));
}
__device__ __forceinline__ float lo2(ull x) { uint32_t a, b; UNPACK2(a, b, x); return __uint_as_float(a); }
__device__ __forceinline__ float hi2(ull x) { uint32_t a, b; UNPACK2(a, b, x); return __uint_as_float(b); }

__device__ __forceinline__ float wsum(float v) {
    v += __shfl_xor_sync(0xffffffffu, v, 16);
    v += __shfl_xor_sync(0xffffffffu, v, 8);
    v += __shfl_xor_sync(0xffffffffu, v, 4);
    v += __shfl_xor_sync(0xffffffffu, v, 2);
    v += __shfl_xor_sync(0xffffffffu, v, 1);
    return v;
}

// F=2 rank-1-per-k outer product over 16 edges (8 f32x2 pairs) for features
// f and f+64. in is [K][RS] transposed (k-major), W is [K][D] row-major.
template<int K>
__device__ __forceinline__ void mm2(const float (*__restrict__ in)[RS],
                                    const float* __restrict__ W,
                                    int f, ull a0[8], ull a1[8]) {
#pragma unroll 2
    for (int k = 0; k < K; k++) {
        ull w0 = dup2(__ldg(&W[k * D + f]));
        ull w1 = dup2(__ldg(&W[k * D + f + 64]));
#pragma unroll
        for (int q = 0; q < 4; q++) {
            ulonglong2 u = *(const ulonglong2*)&in[k][4 * q];
            FMA2(a0[2 * q],     w0, u.x, a0[2 * q]);
            FMA2(a0[2 * q + 1], w0, u.y, a0[2 * q + 1]);
            FMA2(a1[2 * q],     w1, u.x, a1[2 * q]);
            FMA2(a1[2 * q + 1], w1, u.y, a1[2 * q + 1]);
        }
    }
}

// Detect whether edge_index is int64 (high words all zero) or int32.
__global__ void detect_kernel(const int* __restrict__ ei) {
    if (threadIdx.x == 0) {
        int nz = 0;
        for (int i = 1; i < 128; i += 2) nz |= ei[i];
        g_idx64 = (nz == 0) ? 1 : 0;
    }
}

__global__ void zero_kernel(int N) {
    long tot = (long)N * D + (long)N * 3 + N;
    long stride = (long)gridDim.x * blockDim.x;
    for (long i = (long)blockIdx.x * blockDim.x + threadIdx.x; i < tot; i += stride) {
        if (i < (long)N * D)               g_agg_h[i] = 0.0f;
        else if (i < (long)N * D + 3L * N) g_agg_c[i - (long)N * D] = 0.0f;
        else                               g_cnt[i - (long)N * D - 3L * N] = 0.0f;
    }
}

// ---------------- fused edge kernel ----------------
// 64 threads; thread t owns features t and t+64; 16 edges/block as 8 f32x2 pairs.
__global__ __launch_bounds__(64) void edge_kernel(
    const float* __restrict__ h, const void* __restrict__ eiv,
    const float* __restrict__ coord,
    const float* __restrict__ We1, const float* __restrict__ be1,
    const float* __restrict__ We2, const float* __restrict__ be2,
    const float* __restrict__ Watt, const float* __restrict__ batt,
    const float* __restrict__ Wc1, const float* __restrict__ bc1,
    const float* __restrict__ Wc2,
    float* __restrict__ out_ef, int E)
{
    __shared__ __align__(16) float in_t[257][RS];   // [k][e]; rows 0-127 reused as mij
    __shared__ __align__(16) float hid_t[128][RS];  // layer-1 output, transposed
    __shared__ float red_s[2][EPB];
    __shared__ float att_s[EPB];
    __shared__ float cw_s[EPB];
    __shared__ float cd_s[EPB][3];
    __shared__ int   row_s[EPB], col_s[EPB];

    const int t = threadIdx.x;     // 0..63
    const int lane = t & 31;
    const int warp = t >> 5;
    const long e0 = (long)blockIdx.x * EPB;
    const int idx64 = g_idx64;

    // edge indices
    if (t < EPB) {
        long e = e0 + t;
        int r = 0, c = 0;
        if (e < E) {
            if (idx64) {
                const long long* ei = (const long long*)eiv;
                r = (int)ei[e];
                c = (int)ei[(long)E + e];
            } else {
                const int* ei = (const int*)eiv;
                r = ei[e];
                c = ei[(long)E + e];
            }
        }
        row_s[t] = r;
        col_s[t] = c;
    }
    __syncthreads();

    // gather h rows into transposed tile (coalesced LDG)
#pragma unroll
    for (int e = 0; e < EPB; e++) {
        long ro = (long)row_s[e] * D;
        long co = (long)col_s[e] * D;
        in_t[t][e]        = h[ro + t];
        in_t[t + 64][e]   = h[ro + t + 64];
        in_t[128 + t][e]  = h[co + t];
        in_t[192 + t][e]  = h[co + t + 64];
    }
    if (t < EPB * 3) {
        int e = t / 3, d = t % 3;
        cd_s[e][d] = coord[(long)row_s[e] * 3 + d] - coord[(long)col_s[e] * 3 + d];
    }
    __syncthreads();
    if (t < EPB) {
        float x = cd_s[t][0], y = cd_s[t][1], z = cd_s[t][2];
        in_t[256][t] = x * x + y * y + z * z;   // radial
    }
    __syncthreads();

    ull a0[8], a1[8];

    // ---- edge_mlp layer 1: [2D+1] -> D, SiLU ----
#pragma unroll
    for (int j = 0; j < 8; j++) { a0[j] = 0ull; a1[j] = 0ull; }
    mm2<257>(in_t, We1, t, a0, a1);
    {
        ull b0 = dup2(be1[t]), b1 = dup2(be1[t + 64]);
#pragma unroll
        for (int j = 0; j < 8; j++) {
            ADD2(a0[j], a0[j], b0); a0[j] = silu2(a0[j]); st2(&hid_t[t][2 * j], a0[j]);
            ADD2(a1[j], a1[j], b1); a1[j] = silu2(a1[j]); st2(&hid_t[t + 64][2 * j], a1[j]);
        }
    }
    __syncthreads();

    // ---- edge_mlp layer 2: D -> D, SiLU; store mij into in_t rows 0-127 ----
#pragma unroll
    for (int j = 0; j < 8; j++) { a0[j] = 0ull; a1[j] = 0ull; }
    mm2<128>(hid_t, We2, t, a0, a1);
    {
        ull b0 = dup2(be2[t]), b1 = dup2(be2[t + 64]);
#pragma unroll
        for (int j = 0; j < 8; j++) {
            ADD2(a0[j], a0[j], b0); a0[j] = silu2(a0[j]); st2(&in_t[t][2 * j], a0[j]);
            ADD2(a1[j], a1[j], b1); a1[j] = silu2(a1[j]); st2(&in_t[t + 64][2 * j], a1[j]);
        }
    }

    // ---- attention partials from live accumulators ----
    {
        ull wa0 = dup2(Watt[t]), wa1 = dup2(Watt[t + 64]);
#pragma unroll
        for (int j = 0; j < 8; j++) {
            ull s; MUL2(s, a0[j], wa0); FMA2(s, a1[j], wa1, s);
            float r0 = wsum(lo2(s));
            float r1 = wsum(hi2(s));
            if (lane == 0) { red_s[warp][2 * j] = r0; red_s[warp][2 * j + 1] = r1; }
        }
    }
    __syncthreads();   // also publishes mij in in_t
    if (t < EPB)
        att_s[t] = sigm(red_s[0][t] + red_s[1][t] + batt[0]);
    __syncthreads();

    // ---- edge_feat = mij * att: write output + scatter early (overlap atomics) ----
#pragma unroll
    for (int j = 0; j < 8; j++) {
        ull ap = pack2f(att_s[2 * j], att_s[2 * j + 1]);
        ull m0 = *(const ull*)&in_t[t][2 * j];
        ull m1 = *(const ull*)&in_t[t + 64][2 * j];
        ull ef0, ef1; MUL2(ef0, m0, ap); MUL2(ef1, m1, ap);
        long eA = e0 + 2 * j, eB = eA + 1;
        if (eA < E) {
            float v0 = lo2(ef0), v1 = lo2(ef1);
            out_ef[eA * D + t]      = v0;
            out_ef[eA * D + t + 64] = v1;
            long rb = (long)row_s[2 * j] * D;
            atomicAdd(&g_agg_h[rb + t], v0);
            atomicAdd(&g_agg_h[rb + t + 64], v1);
        }
        if (eB < E) {
            float v0 = hi2(ef0), v1 = hi2(ef1);
            out_ef[eB * D + t]      = v0;
            out_ef[eB * D + t + 64] = v1;
            long rb = (long)row_s[2 * j + 1] * D;
            atomicAdd(&g_agg_h[rb + t], v0);
            atomicAdd(&g_agg_h[rb + t + 64], v1);
        }
    }

    // ---- coord_mlp: cw = silu(edge_feat @ Wc1 + bc1) @ Wc2 ----
    // edge_feat = att * mij, so dot(edge_feat, Wc1col) = att * dot(mij, Wc1col)
#pragma unroll
    for (int j = 0; j < 8; j++) { a0[j] = 0ull; a1[j] = 0ull; }
    mm2<128>(in_t, Wc1, t, a0, a1);
    {
        float bcl0 = bc1[t], bcl1 = bc1[t + 64];
        float wc0  = Wc2[t], wc1v = Wc2[t + 64];
#pragma unroll
        for (int j = 0; j < 8; j++) {
            float d00 = lo2(a0[j]), d01 = hi2(a0[j]);
            float d10 = lo2(a1[j]), d11 = hi2(a1[j]);
            float aA = att_s[2 * j], aB = att_s[2 * j + 1];
            float s0 = siluf(fmaf(aA, d00, bcl0)) * wc0 + siluf(fmaf(aA, d10, bcl1)) * wc1v;
            float s1 = siluf(fmaf(aB, d01, bcl0)) * wc0 + siluf(fmaf(aB, d11, bcl1)) * wc1v;
            float r0 = wsum(s0);
            float r1 = wsum(s1);
            if (lane == 0) { red_s[warp][2 * j] = r0; red_s[warp][2 * j + 1] = r1; }
        }
    }
    __syncthreads();
    if (t < EPB)
        cw_s[t] = red_s[0][t] + red_s[1][t];
    __syncthreads();

    // ---- trans = clip(coord_diff * cw, +/-10); scatter into agg_c, cnt ----
    if (t < EPB * 3) {
        int e = t / 3, d = t % 3;
        long eg = e0 + e;
        if (eg < E) {
            float tr = cd_s[e][d] * cw_s[e];
            tr = fminf(10.0f, fmaxf(-10.0f, tr));
            atomicAdd(&g_agg_c[(long)row_s[e] * 3 + d], tr);
        }
    }
    if (t < EPB) {
        long eg = e0 + t;
        if (eg < E) atomicAdd(&g_cnt[row_s[t]], 1.0f);
    }
}

// ---------------- node kernel: h_out = h + node_mlp([h, agg]) ----------------
__global__ __launch_bounds__(64) void node_kernel(
    const float* __restrict__ h,
    const float* __restrict__ Wn1, const float* __restrict__ bn1,
    const float* __restrict__ Wn2, const float* __restrict__ bn2,
    float* __restrict__ h_out, int N)
{
    __shared__ __align__(16) float in_t[256][RS];
    __shared__ __align__(16) float hid_t[128][RS];

    const int t = threadIdx.x;     // 0..63
    const long n0 = (long)blockIdx.x * EPB;

#pragma unroll
    for (int e = 0; e < EPB; e++) {
        long n = n0 + e;
        if (n >= N) n = N - 1;
        long nb = n * D;
        in_t[t][e]        = h[nb + t];
        in_t[t + 64][e]   = h[nb + t + 64];
        in_t[128 + t][e]  = g_agg_h[nb + t];
        in_t[192 + t][e]  = g_agg_h[nb + t + 64];
    }
    __syncthreads();

    ull a0[8], a1[8];
#pragma unroll
    for (int j = 0; j < 8; j++) { a0[j] = 0ull; a1[j] = 0ull; }
    mm2<256>(in_t, Wn1, t, a0, a1);
    {
        ull b0 = dup2(bn1[t]), b1 = dup2(bn1[t + 64]);
#pragma unroll
        for (int j = 0; j < 8; j++) {
            ADD2(a0[j], a0[j], b0); st2(&hid_t[t][2 * j],      silu2(a0[j]));
            ADD2(a1[j], a1[j], b1); st2(&hid_t[t + 64][2 * j], silu2(a1[j]));
        }
    }
    __syncthreads();

#pragma unroll
    for (int j = 0; j < 8; j++) { a0[j] = 0ull; a1[j] = 0ull; }
    mm2<128>(hid_t, Wn2, t, a0, a1);
    {
        float b20 = bn2[t], b21 = bn2[t + 64];
#pragma unroll
        for (int j = 0; j < 8; j++) {
            long nA = n0 + 2 * j, nB = nA + 1;
            if (nA < N) {
                h_out[nA * D + t]      = in_t[t][2 * j]      + lo2(a0[j]) + b20;
                h_out[nA * D + t + 64] = in_t[t + 64][2 * j] + lo2(a1[j]) + b21;
            }
            if (nB < N) {
                h_out[nB * D + t]      = in_t[t][2 * j + 1]      + hi2(a0[j]) + b20;
                h_out[nB * D + t + 64] = in_t[t + 64][2 * j + 1] + hi2(a1[j]) + b21;
            }
        }
    }
}

// ---------------- coord finalize: coord + clip(agg_c / max(cnt,1), +/-10) ----
__global__ void coord_kernel(const float* __restrict__ coord,
                             float* __restrict__ coord_out, int N)
{
    int i = blockIdx.x * blockDim.x + threadIdx.x;
    if (i < N * 3) {
        int n = i / 3;
        float m = g_agg_c[i] / fmaxf(g_cnt[n], 1.0f);
        m = fminf(10.0f, fmaxf(-10.0f, m));
        coord_out[i] = coord[i] + m;
    }
}

// ---------------- launch ----------------
extern "C" void kernel_launch(void* const* d_in, const int* in_sizes, int n_in,
                              void* d_out, int out_size)
{
    const float* h     = (const float*)d_in[0];
    const void*  ei    = d_in[1];
    const float* coord = (const float*)d_in[2];
    const float* We1   = (const float*)d_in[3];
    const float* be1   = (const float*)d_in[4];
    const float* We2   = (const float*)d_in[5];
    const float* be2   = (const float*)d_in[6];
    const float* Watt  = (const float*)d_in[7];
    const float* batt  = (const float*)d_in[8];
    const float* Wc1   = (const float*)d_in[9];
    const float* bc1   = (const float*)d_in[10];
    const float* Wc2   = (const float*)d_in[11];
    const float* Wn1   = (const float*)d_in[12];
    const float* bn1   = (const float*)d_in[13];
    const float* Wn2   = (const float*)d_in[14];
    const float* bn2   = (const float*)d_in[15];

    const int N = in_sizes[0] / D;
    const int E = in_sizes[1] / 2;

    float* out       = (float*)d_out;
    float* h_out     = out;
    float* coord_out = out + (long)N * D;
    float* out_ef    = out + (long)N * D + (long)N * 3;

    detect_kernel<<<1, 32>>>((const int*)ei);
    zero_kernel<<<1024, 256>>>(N);

    int eb = (E + EPB - 1) / EPB;
    edge_kernel<<<eb, 64>>>(h, ei, coord,
                            We1, be1, We2, be2, Watt, batt,
                            Wc1, bc1, Wc2, out_ef, E);

    int nb = (N + EPB - 1) / EPB;
    node_kernel<<<nb, 64>>>(h, Wn1, bn1, Wn2, bn2, h_out, N);

    coord_kernel<<<(N * 3 + 255) / 256, 256>>>(coord, coord_out, N);
}

// round 9
// speedup vs baseline: 1.4413x; 1.2404x over previous
#include <cuda_runtime.h>
#include <stdint.h>

#define D 128
#define MAX_N 50000
#define MAX_E 500000
#define EPB 16
#define RS 20   // padded row stride (floats); multiple of 4 keeps LDS.128 alignment

// ---------------- scratch (no allocation allowed) ----------------
__device__ float g_agg_h[(size_t)MAX_N * D];   // segment_sum(edge_feat, row)
__device__ float g_agg_c[MAX_N * 3];           // segment_sum(trans, row)
__device__ float g_cnt[MAX_N];                 // per-row edge count
__device__ int   g_idx64;                      // 1 if edge_index is int64

typedef unsigned long long ull;

// ---------------- packed f32x2 helpers ----------------
#define PACK2(d, lo, hi)   asm("mov.b64 %0, {%1, %2};" : "=l"(d) : "r"(lo), "r"(hi))
#define UNPACK2(lo, hi, s) asm("mov.b64 {%0, %1}, %2;" : "=r"(lo), "=r"(hi) : "l"(s))
#define FMA2(d, a, b, c)   asm("fma.rn.f32x2 %0, %1, %2, %3;" : "=l"(d) : "l"(a), "l"(b), "l"(c))
#define ADD2(d, a, b)      asm("add.rn.f32x2 %0, %1, %2;" : "=l"(d) : "l"(a), "l"(b))
#define MUL2(d, a, b)      asm("mul.rn.f32x2 %0, %1, %2;" : "=l"(d) : "l"(a), "l"(b))

__device__ __forceinline__ float siluf(float x) { return x / (1.0f + __expf(-x)); }
__device__ __forceinline__ float sigm(float x)  { return 1.0f / (1.0f + __expf(-x)); }

__device__ __forceinline__ ull dup2(float x) {
    ull r; uint32_t u = __float_as_uint(x);
    PACK2(r, u, u);
    return r;
}
__device__ __forceinline__ ull pack2f(float a, float b) {
    ull r; PACK2(r, __float_as_uint(a), __float_as_uint(b));
    return r;
}
__device__ __forceinline__ ull silu2(ull x) {
    uint32_t a, b; UNPACK2(a, b, x);
    uint32_t u0 = __float_as_uint(siluf(__uint_as_float(a)));
    uint32_t u1 = __float_as_uint(siluf(__uint_as_float(b)));
    ull r; PACK2(r, u0, u1);
    return r;
}
__device__ __forceinline__ void st2(float* p, ull x) {
    uint32_t a, b; UNPACK2(a, b, x);
    *(float2*)p = make_float2(__uint_as_float(a), __uint_as_float(b));
}
__device__ __forceinline__ float lo2(ull x) { uint32_t a, b; UNPACK2(a, b, x); return __uint_as_float(a); }
__device__ __forceinline__ float hi2(ull x) { uint32_t a, b; UNPACK2(a, b, x); return __uint_as_float(b); }

__device__ __forceinline__ float wsum(float v) {
    v += __shfl_xor_sync(0xffffffffu, v, 16);
    v += __shfl_xor_sync(0xffffffffu, v, 8);
    v += __shfl_xor_sync(0xffffffffu, v, 4);
    v += __shfl_xor_sync(0xffffffffu, v, 2);
    v += __shfl_xor_sync(0xffffffffu, v, 1);
    return v;
}

// F=2 rank-1-per-k outer product over 16 edges (8 f32x2 pairs) for features
// f and f+64. in is [K][RS] transposed (k-major), W is [K][D] row-major.
template<int K>
__device__ __forceinline__ void mm2(const float (*__restrict__ in)[RS],
                                    const float* __restrict__ W,
                                    int f, ull a0[8], ull a1[8]) {
#pragma unroll 2
    for (int k = 0; k < K; k++) {
        ull w0 = dup2(__ldg(&W[k * D + f]));
        ull w1 = dup2(__ldg(&W[k * D + f + 64]));
#pragma unroll
        for (int q = 0; q < 4; q++) {
            ulonglong2 u = *(const ulonglong2*)&in[k][4 * q];
            FMA2(a0[2 * q],     w0, u.x, a0[2 * q]);
            FMA2(a0[2 * q + 1], w0, u.y, a0[2 * q + 1]);
            FMA2(a1[2 * q],     w1, u.x, a1[2 * q]);
            FMA2(a1[2 * q + 1], w1, u.y, a1[2 * q + 1]);
        }
    }
}

// Detect whether edge_index is int64 (high words all zero) or int32.
__global__ void detect_kernel(const int* __restrict__ ei) {
    if (threadIdx.x == 0) {
        int nz = 0;
        for (int i = 1; i < 128; i += 2) nz |= ei[i];
        g_idx64 = (nz == 0) ? 1 : 0;
    }
}

__global__ void zero_kernel(int N) {
    long tot = (long)N * D + (long)N * 3 + N;
    long stride = (long)gridDim.x * blockDim.x;
    for (long i = (long)blockIdx.x * blockDim.x + threadIdx.x; i < tot; i += stride) {
        if (i < (long)N * D)               g_agg_h[i] = 0.0f;
        else if (i < (long)N * D + 3L * N) g_agg_c[i - (long)N * D] = 0.0f;
        else                               g_cnt[i - (long)N * D - 3L * N] = 0.0f;
    }
}

// ---------------- fused edge kernel ----------------
// 64 threads; thread t owns features t and t+64; 16 edges/block as 8 f32x2 pairs.
// smem: ONE [257][RS] tile. rows 0-127: h_row, later mij. rows 128-255: h_col,
// later layer-1 hidden. row 256: radial.
__global__ __launch_bounds__(64) void edge_kernel(
    const float* __restrict__ h, const void* __restrict__ eiv,
    const float* __restrict__ coord,
    const float* __restrict__ We1, const float* __restrict__ be1,
    const float* __restrict__ We2, const float* __restrict__ be2,
    const float* __restrict__ Watt, const float* __restrict__ batt,
    const float* __restrict__ Wc1, const float* __restrict__ bc1,
    const float* __restrict__ Wc2,
    float* __restrict__ out_ef, int E)
{
    __shared__ __align__(16) float in_t[257][RS];
    __shared__ float red_s[2][EPB];
    __shared__ float att_s[EPB];
    __shared__ float cw_s[EPB];
    __shared__ float cd_s[EPB][3];
    __shared__ int   row_s[EPB], col_s[EPB];

    const int t = threadIdx.x;     // 0..63
    const int lane = t & 31;
    const int warp = t >> 5;
    const long e0 = (long)blockIdx.x * EPB;
    const int idx64 = g_idx64;

    // edge indices
    if (t < EPB) {
        long e = e0 + t;
        int r = 0, c = 0;
        if (e < E) {
            if (idx64) {
                const long long* ei = (const long long*)eiv;
                r = (int)ei[e];
                c = (int)ei[(long)E + e];
            } else {
                const int* ei = (const int*)eiv;
                r = ei[e];
                c = ei[(long)E + e];
            }
        }
        row_s[t] = r;
        col_s[t] = c;
    }
    __syncthreads();

    // gather h rows into transposed tile (coalesced LDG)
#pragma unroll
    for (int e = 0; e < EPB; e++) {
        long ro = (long)row_s[e] * D;
        long co = (long)col_s[e] * D;
        in_t[t][e]        = h[ro + t];
        in_t[t + 64][e]   = h[ro + t + 64];
        in_t[128 + t][e]  = h[co + t];
        in_t[192 + t][e]  = h[co + t + 64];
    }
    if (t < EPB * 3) {
        int e = t / 3, d = t % 3;
        cd_s[e][d] = coord[(long)row_s[e] * 3 + d] - coord[(long)col_s[e] * 3 + d];
    }
    __syncthreads();
    if (t < EPB) {
        float x = cd_s[t][0], y = cd_s[t][1], z = cd_s[t][2];
        in_t[256][t] = x * x + y * y + z * z;   // radial
    }
    __syncthreads();

    ull a0[8], a1[8];

    // ---- edge_mlp layer 1: [2D+1] -> D, SiLU ----
#pragma unroll
    for (int j = 0; j < 8; j++) { a0[j] = 0ull; a1[j] = 0ull; }
    mm2<257>(in_t, We1, t, a0, a1);
    __syncthreads();   // all reads of in_t done; rows 128-255 become hid storage
    {
        ull b0 = dup2(be1[t]), b1 = dup2(be1[t + 64]);
#pragma unroll
        for (int j = 0; j < 8; j++) {
            ADD2(a0[j], a0[j], b0); a0[j] = silu2(a0[j]); st2(&in_t[128 + t][2 * j], a0[j]);
            ADD2(a1[j], a1[j], b1); a1[j] = silu2(a1[j]); st2(&in_t[192 + t][2 * j], a1[j]);
        }
    }
    __syncthreads();

    // ---- edge_mlp layer 2: D -> D, SiLU; hid = rows 128-255, mij -> rows 0-127 ----
#pragma unroll
    for (int j = 0; j < 8; j++) { a0[j] = 0ull; a1[j] = 0ull; }
    mm2<128>((const float (*)[RS])(in_t + 128), We2, t, a0, a1);
    {
        ull b0 = dup2(be2[t]), b1 = dup2(be2[t + 64]);
#pragma unroll
        for (int j = 0; j < 8; j++) {
            ADD2(a0[j], a0[j], b0); a0[j] = silu2(a0[j]); st2(&in_t[t][2 * j], a0[j]);
            ADD2(a1[j], a1[j], b1); a1[j] = silu2(a1[j]); st2(&in_t[t + 64][2 * j], a1[j]);
        }
    }

    // ---- attention partials from live accumulators ----
    {
        ull wa0 = dup2(Watt[t]), wa1 = dup2(Watt[t + 64]);
#pragma unroll
        for (int j = 0; j < 8; j++) {
            ull s; MUL2(s, a0[j], wa0); FMA2(s, a1[j], wa1, s);
            float r0 = wsum(lo2(s));
            float r1 = wsum(hi2(s));
            if (lane == 0) { red_s[warp][2 * j] = r0; red_s[warp][2 * j + 1] = r1; }
        }
    }
    __syncthreads();   // also publishes mij in rows 0-127
    if (t < EPB)
        att_s[t] = sigm(red_s[0][t] + red_s[1][t] + batt[0]);
    __syncthreads();

    // ---- edge_feat = mij * att: write output + scatter early (overlap atomics) ----
#pragma unroll
    for (int j = 0; j < 8; j++) {
        ull ap = pack2f(att_s[2 * j], att_s[2 * j + 1]);
        ull m0 = *(const ull*)&in_t[t][2 * j];
        ull m1 = *(const ull*)&in_t[t + 64][2 * j];
        ull ef0, ef1; MUL2(ef0, m0, ap); MUL2(ef1, m1, ap);
        long eA = e0 + 2 * j, eB = eA + 1;
        if (eA < E) {
            float v0 = lo2(ef0), v1 = lo2(ef1);
            out_ef[eA * D + t]      = v0;
            out_ef[eA * D + t + 64] = v1;
            long rb = (long)row_s[2 * j] * D;
            atomicAdd(&g_agg_h[rb + t], v0);
            atomicAdd(&g_agg_h[rb + t + 64], v1);
        }
        if (eB < E) {
            float v0 = hi2(ef0), v1 = hi2(ef1);
            out_ef[eB * D + t]      = v0;
            out_ef[eB * D + t + 64] = v1;
            long rb = (long)row_s[2 * j + 1] * D;
            atomicAdd(&g_agg_h[rb + t], v0);
            atomicAdd(&g_agg_h[rb + t + 64], v1);
        }
    }

    // ---- coord_mlp: cw = silu(edge_feat @ Wc1 + bc1) @ Wc2 ----
    // edge_feat = att * mij, so dot(edge_feat, Wc1col) = att * dot(mij, Wc1col)
#pragma unroll
    for (int j = 0; j < 8; j++) { a0[j] = 0ull; a1[j] = 0ull; }
    mm2<128>(in_t, Wc1, t, a0, a1);
    {
        float bcl0 = bc1[t], bcl1 = bc1[t + 64];
        float wc0  = Wc2[t], wc1v = Wc2[t + 64];
#pragma unroll
        for (int j = 0; j < 8; j++) {
            float d00 = lo2(a0[j]), d01 = hi2(a0[j]);
            float d10 = lo2(a1[j]), d11 = hi2(a1[j]);
            float aA = att_s[2 * j], aB = att_s[2 * j + 1];
            float s0 = siluf(fmaf(aA, d00, bcl0)) * wc0 + siluf(fmaf(aA, d10, bcl1)) * wc1v;
            float s1 = siluf(fmaf(aB, d01, bcl0)) * wc0 + siluf(fmaf(aB, d11, bcl1)) * wc1v;
            float r0 = wsum(s0);
            float r1 = wsum(s1);
            if (lane == 0) { red_s[warp][2 * j] = r0; red_s[warp][2 * j + 1] = r1; }
        }
    }
    __syncthreads();
    if (t < EPB)
        cw_s[t] = red_s[0][t] + red_s[1][t];
    __syncthreads();

    // ---- trans = clip(coord_diff * cw, +/-10); scatter into agg_c, cnt ----
    if (t < EPB * 3) {
        int e = t / 3, d = t % 3;
        long eg = e0 + e;
        if (eg < E) {
            float tr = cd_s[e][d] * cw_s[e];
            tr = fminf(10.0f, fmaxf(-10.0f, tr));
            atomicAdd(&g_agg_c[(long)row_s[e] * 3 + d], tr);
        }
    }
    if (t < EPB) {
        long eg = e0 + t;
        if (eg < E) atomicAdd(&g_cnt[row_s[t]], 1.0f);
    }
}

// ---------------- node kernel: h_out = h + node_mlp([h, agg]) ----------------
// Same aliasing: rows 0-127 h (kept for residual), rows 128-255 agg -> hid.
__global__ __launch_bounds__(64) void node_kernel(
    const float* __restrict__ h,
    const float* __restrict__ Wn1, const float* __restrict__ bn1,
    const float* __restrict__ Wn2, const float* __restrict__ bn2,
    float* __restrict__ h_out, int N)
{
    __shared__ __align__(16) float in_t[256][RS];

    const int t = threadIdx.x;     // 0..63
    const long n0 = (long)blockIdx.x * EPB;

#pragma unroll
    for (int e = 0; e < EPB; e++) {
        long n = n0 + e;
        if (n >= N) n = N - 1;
        long nb = n * D;
        in_t[t][e]        = h[nb + t];
        in_t[t + 64][e]   = h[nb + t + 64];
        in_t[128 + t][e]  = g_agg_h[nb + t];
        in_t[192 + t][e]  = g_agg_h[nb + t + 64];
    }
    __syncthreads();

    ull a0[8], a1[8];
#pragma unroll
    for (int j = 0; j < 8; j++) { a0[j] = 0ull; a1[j] = 0ull; }
    mm2<256>(in_t, Wn1, t, a0, a1);
    __syncthreads();   // reads done; rows 128-255 become hid storage
    {
        ull b0 = dup2(bn1[t]), b1 = dup2(bn1[t + 64]);
#pragma unroll
        for (int j = 0; j < 8; j++) {
            ADD2(a0[j], a0[j], b0); st2(&in_t[128 + t][2 * j], silu2(a0[j]));
            ADD2(a1[j], a1[j], b1); st2(&in_t[192 + t][2 * j], silu2(a1[j]));
        }
    }
    __syncthreads();

#pragma unroll
    for (int j = 0; j < 8; j++) { a0[j] = 0ull; a1[j] = 0ull; }
    mm2<128>((const float (*)[RS])(in_t + 128), Wn2, t, a0, a1);
    {
        float b20 = bn2[t], b21 = bn2[t + 64];
#pragma unroll
        for (int j = 0; j < 8; j++) {
            long nA = n0 + 2 * j, nB = nA + 1;
            if (nA < N) {
                h_out[nA * D + t]      = in_t[t][2 * j]      + lo2(a0[j]) + b20;
                h_out[nA * D + t + 64] = in_t[t + 64][2 * j] + lo2(a1[j]) + b21;
            }
            if (nB < N) {
                h_out[nB * D + t]      = in_t[t][2 * j + 1]      + hi2(a0[j]) + b20;
                h_out[nB * D + t + 64] = in_t[t + 64][2 * j + 1] + hi2(a1[j]) + b21;
            }
        }
    }
}

// ---------------- coord finalize: coord + clip(agg_c / max(cnt,1), +/-10) ----
__global__ void coord_kernel(const float* __restrict__ coord,
                             float* __restrict__ coord_out, int N)
{
    int i = blockIdx.x * blockDim.x + threadIdx.x;
    if (i < N * 3) {
        int n = i / 3;
        float m = g_agg_c[i] / fmaxf(g_cnt[n], 1.0f);
        m = fminf(10.0f, fmaxf(-10.0f, m));
        coord_out[i] = coord[i] + m;
    }
}

// ---------------- launch ----------------
extern "C" void kernel_launch(void* const* d_in, const int* in_sizes, int n_in,
                              void* d_out, int out_size)
{
    const float* h     = (const float*)d_in[0];
    const void*  ei    = d_in[1];
    const float* coord = (const float*)d_in[2];
    const float* We1   = (const float*)d_in[3];
    const float* be1   = (const float*)d_in[4];
    const float* We2   = (const float*)d_in[5];
    const float* be2   = (const float*)d_in[6];
    const float* Watt  = (const float*)d_in[7];
    const float* batt  = (const float*)d_in[8];
    const float* Wc1   = (const float*)d_in[9];
    const float* bc1   = (const float*)d_in[10];
    const float* Wc2   = (const float*)d_in[11];
    const float* Wn1   = (const float*)d_in[12];
    const float* bn1   = (const float*)d_in[13];
    const float* Wn2   = (const float*)d_in[14];
    const float* bn2   = (const float*)d_in[15];

    const int N = in_sizes[0] / D;
    const int E = in_sizes[1] / 2;

    float* out       = (float*)d_out;
    float* h_out     = out;
    float* coord_out = out + (long)N * D;
    float* out_ef    = out + (long)N * D + (long)N * 3;

    detect_kernel<<<1, 32>>>((const int*)ei);
    zero_kernel<<<1024, 256>>>(N);

    int eb = (E + EPB - 1) / EPB;
    edge_kernel<<<eb, 64>>>(h, ei, coord,
                            We1, be1, We2, be2, Watt, batt,
                            Wc1, bc1, Wc2, out_ef, E);

    int nb = (N + EPB - 1) / EPB;
    node_kernel<<<nb, 64>>>(h, Wn1, bn1, Wn2, bn2, h_out, N);

    coord_kernel<<<(N * 3 + 255) / 256, 256>>>(coord, coord_out, N);
}

// round 11
// speedup vs baseline: 1.7130x; 1.1885x over previous
#include <cuda_runtime.h>
#include <stdint.h>

#define D 128
#define MAX_N 50000
#define MAX_E 500000
#define EPB 16
#define RS 20   // padded row stride (floats); multiple of 4 keeps LDS.128 alignment

// ---------------- scratch (no allocation allowed) ----------------
__device__ float g_agg_h[(size_t)MAX_N * D];   // segment_sum(edge_feat, row)
__device__ float g_agg_c[MAX_N * 3];           // segment_sum(trans, row)
__device__ float g_cnt[MAX_N];                 // per-row edge count
__device__ int   g_idx64;                      // 1 if edge_index is int64

typedef unsigned long long ull;

// ---------------- packed f32x2 helpers ----------------
#define PACK2(d, lo, hi)   asm("mov.b64 %0, {%1, %2};" : "=l"(d) : "r"(lo), "r"(hi))
#define UNPACK2(lo, hi, s) asm("mov.b64 {%0, %1}, %2;" : "=r"(lo), "=r"(hi) : "l"(s))
#define FMA2(d, a, b, c)   asm("fma.rn.f32x2 %0, %1, %2, %3;" : "=l"(d) : "l"(a), "l"(b), "l"(c))
#define ADD2(d, a, b)      asm("add.rn.f32x2 %0, %1, %2;" : "=l"(d) : "l"(a), "l"(b))
#define MUL2(d, a, b)      asm("mul.rn.f32x2 %0, %1, %2;" : "=l"(d) : "l"(a), "l"(b))

__device__ __forceinline__ float siluf(float x) { return x / (1.0f + __expf(-x)); }
__device__ __forceinline__ float sigm(float x)  { return 1.0f / (1.0f + __expf(-x)); }

__device__ __forceinline__ ull dup2(float x) {
    ull r; uint32_t u = __float_as_uint(x);
    PACK2(r, u, u);
    return r;
}
__device__ __forceinline__ ull pack2f(float a, float b) {
    ull r; PACK2(r, __float_as_uint(a), __float_as_uint(b));
    return r;
}
__device__ __forceinline__ ull silu2(ull x) {
    uint32_t a, b; UNPACK2(a, b, x);
    uint32_t u0 = __float_as_uint(siluf(__uint_as_float(a)));
    uint32_t u1 = __float_as_uint(siluf(__uint_as_float(b)));
    ull r; PACK2(r, u0, u1);
    return r;
}
__device__ __forceinline__ void st2(float* p, ull x) {
    uint32_t a, b; UNPACK2(a, b, x);
    *(float2*)p = make_float2(__uint_as_float(a), __uint_as_float(b));
}
__device__ __forceinline__ float lo2(ull x) { uint32_t a, b; UNPACK2(a, b, x); return __uint_as_float(a); }
__device__ __forceinline__ float hi2(ull x) { uint32_t a, b; UNPACK2(a, b, x); return __uint_as_float(b); }

__device__ __forceinline__ float wsum(float v) {
    v += __shfl_xor_sync(0xffffffffu, v, 16);
    v += __shfl_xor_sync(0xffffffffu, v, 8);
    v += __shfl_xor_sync(0xffffffffu, v, 4);
    v += __shfl_xor_sync(0xffffffffu, v, 2);
    v += __shfl_xor_sync(0xffffffffu, v, 1);
    return v;
}

// F=2 rank-1-per-k outer product over 16 edges (8 f32x2 pairs) for ADJACENT
// features f2 and f2+1 (one float2 weight LDG per k, software-prefetched).
// in is [K][RS] transposed (k-major), W is [K][D] row-major.
template<int K>
__device__ __forceinline__ void mm2(const float (*__restrict__ in)[RS],
                                    const float* __restrict__ W,
                                    int f2, ull a0[8], ull a1[8]) {
    const float* wp = W + f2;
    float2 w = *(const float2*)wp;
    wp += D;
#pragma unroll 4
    for (int k = 0; k < K - 1; k++) {
        float2 wn = *(const float2*)wp;     // prefetch next k's weights
        wp += D;
        ull w0 = dup2(w.x), w1 = dup2(w.y);
        const float* rp = in[k];
#pragma unroll
        for (int q = 0; q < 4; q++) {
            ulonglong2 u = *(const ulonglong2*)(rp + 4 * q);
            FMA2(a0[2 * q],     w0, u.x, a0[2 * q]);
            FMA2(a0[2 * q + 1], w0, u.y, a0[2 * q + 1]);
            FMA2(a1[2 * q],     w1, u.x, a1[2 * q]);
            FMA2(a1[2 * q + 1], w1, u.y, a1[2 * q + 1]);
        }
        w = wn;
    }
    {
        ull w0 = dup2(w.x), w1 = dup2(w.y);
        const float* rp = in[K - 1];
#pragma unroll
        for (int q = 0; q < 4; q++) {
            ulonglong2 u = *(const ulonglong2*)(rp + 4 * q);
            FMA2(a0[2 * q],     w0, u.x, a0[2 * q]);
            FMA2(a0[2 * q + 1], w0, u.y, a0[2 * q + 1]);
            FMA2(a1[2 * q],     w1, u.x, a1[2 * q]);
            FMA2(a1[2 * q + 1], w1, u.y, a1[2 * q + 1]);
        }
    }
}

// Detect whether edge_index is int64 (high words all zero) or int32.
__global__ void detect_kernel(const int* __restrict__ ei) {
    if (threadIdx.x == 0) {
        int nz = 0;
        for (int i = 1; i < 128; i += 2) nz |= ei[i];
        g_idx64 = (nz == 0) ? 1 : 0;
    }
}

__global__ void zero_kernel(int N) {
    long tot = (long)N * D + (long)N * 3 + N;
    long stride = (long)gridDim.x * blockDim.x;
    for (long i = (long)blockIdx.x * blockDim.x + threadIdx.x; i < tot; i += stride) {
        if (i < (long)N * D)               g_agg_h[i] = 0.0f;
        else if (i < (long)N * D + 3L * N) g_agg_c[i - (long)N * D] = 0.0f;
        else                               g_cnt[i - (long)N * D - 3L * N] = 0.0f;
    }
}

// ---------------- fused edge kernel ----------------
// 64 threads; thread t owns features 2t and 2t+1; 16 edges/block as 8 f32x2 pairs.
// smem: ONE [257][RS] tile. rows 0-127: h_row, later mij. rows 128-255: h_col,
// later layer-1 hidden. row 256: radial.
__global__ __launch_bounds__(64, 10) void edge_kernel(
    const float* __restrict__ h, const void* __restrict__ eiv,
    const float* __restrict__ coord,
    const float* __restrict__ We1, const float* __restrict__ be1,
    const float* __restrict__ We2, const float* __restrict__ be2,
    const float* __restrict__ Watt, const float* __restrict__ batt,
    const float* __restrict__ Wc1, const float* __restrict__ bc1,
    const float* __restrict__ Wc2,
    float* __restrict__ out_ef, int E)
{
    __shared__ __align__(16) float in_t[257][RS];
    __shared__ float red_s[2][EPB];
    __shared__ float att_s[EPB];
    __shared__ float cw_s[EPB];
    __shared__ float cd_s[EPB][3];
    __shared__ int   row_s[EPB], col_s[EPB];

    const int t = threadIdx.x;     // 0..63
    const int lane = t & 31;
    const int warp = t >> 5;
    const int f2 = 2 * t;          // features f2, f2+1
    const long e0 = (long)blockIdx.x * EPB;
    const int idx64 = g_idx64;

    // edge indices
    if (t < EPB) {
        long e = e0 + t;
        int r = 0, c = 0;
        if (e < E) {
            if (idx64) {
                const long long* ei = (const long long*)eiv;
                r = (int)ei[e];
                c = (int)ei[(long)E + e];
            } else {
                const int* ei = (const int*)eiv;
                r = ei[e];
                c = ei[(long)E + e];
            }
        }
        row_s[t] = r;
        col_s[t] = c;
    }
    __syncthreads();

    // gather h rows into transposed tile (coalesced LDG)
#pragma unroll
    for (int e = 0; e < EPB; e++) {
        long ro = (long)row_s[e] * D;
        long co = (long)col_s[e] * D;
        in_t[t][e]        = h[ro + t];
        in_t[t + 64][e]   = h[ro + t + 64];
        in_t[128 + t][e]  = h[co + t];
        in_t[192 + t][e]  = h[co + t + 64];
    }
    if (t < EPB * 3) {
        int e = t / 3, d = t % 3;
        cd_s[e][d] = coord[(long)row_s[e] * 3 + d] - coord[(long)col_s[e] * 3 + d];
    }
    __syncthreads();
    if (t < EPB) {
        float x = cd_s[t][0], y = cd_s[t][1], z = cd_s[t][2];
        in_t[256][t] = x * x + y * y + z * z;   // radial
    }
    __syncthreads();

    ull a0[8], a1[8];

    // ---- edge_mlp layer 1: [2D+1] -> D, SiLU ----
#pragma unroll
    for (int j = 0; j < 8; j++) { a0[j] = 0ull; a1[j] = 0ull; }
    mm2<257>(in_t, We1, f2, a0, a1);
    __syncthreads();   // all reads of in_t done; rows 128-255 become hid storage
    {
        float2 b = *(const float2*)&be1[f2];
        ull b0 = dup2(b.x), b1 = dup2(b.y);
#pragma unroll
        for (int j = 0; j < 8; j++) {
            ADD2(a0[j], a0[j], b0); a0[j] = silu2(a0[j]); st2(&in_t[128 + f2][2 * j], a0[j]);
            ADD2(a1[j], a1[j], b1); a1[j] = silu2(a1[j]); st2(&in_t[129 + f2][2 * j], a1[j]);
        }
    }
    __syncthreads();

    // ---- edge_mlp layer 2: D -> D, SiLU; hid = rows 128-255, mij -> rows 0-127 ----
#pragma unroll
    for (int j = 0; j < 8; j++) { a0[j] = 0ull; a1[j] = 0ull; }
    mm2<128>((const float (*)[RS])(in_t + 128), We2, f2, a0, a1);
    {
        float2 b = *(const float2*)&be2[f2];
        ull b0 = dup2(b.x), b1 = dup2(b.y);
#pragma unroll
        for (int j = 0; j < 8; j++) {
            ADD2(a0[j], a0[j], b0); a0[j] = silu2(a0[j]); st2(&in_t[f2][2 * j], a0[j]);
            ADD2(a1[j], a1[j], b1); a1[j] = silu2(a1[j]); st2(&in_t[f2 + 1][2 * j], a1[j]);
        }
    }

    // ---- attention partials from live accumulators ----
    {
        float2 wa = *(const float2*)&Watt[f2];
        ull wa0 = dup2(wa.x), wa1 = dup2(wa.y);
#pragma unroll
        for (int j = 0; j < 8; j++) {
            ull s; MUL2(s, a0[j], wa0); FMA2(s, a1[j], wa1, s);
            float r0 = wsum(lo2(s));
            float r1 = wsum(hi2(s));
            if (lane == 0) { red_s[warp][2 * j] = r0; red_s[warp][2 * j + 1] = r1; }
        }
    }
    __syncthreads();   // also publishes mij in rows 0-127
    if (t < EPB)
        att_s[t] = sigm(red_s[0][t] + red_s[1][t] + batt[0]);
    __syncthreads();

    // ---- edge_feat = mij * att: write output + scatter early (overlap atomics) ----
#pragma unroll
    for (int j = 0; j < 8; j++) {
        ull ap = pack2f(att_s[2 * j], att_s[2 * j + 1]);
        ull m0 = *(const ull*)&in_t[f2][2 * j];        // feature f2, edges (eA,eB)
        ull m1 = *(const ull*)&in_t[f2 + 1][2 * j];    // feature f2+1
        ull ef0, ef1; MUL2(ef0, m0, ap); MUL2(ef1, m1, ap);
        long eA = e0 + 2 * j, eB = eA + 1;
        if (eA < E) {
            float v0 = lo2(ef0), v1 = lo2(ef1);
            *(float2*)&out_ef[eA * D + f2] = make_float2(v0, v1);
            long rb = (long)row_s[2 * j] * D;
            atomicAdd(&g_agg_h[rb + f2], v0);
            atomicAdd(&g_agg_h[rb + f2 + 1], v1);
        }
        if (eB < E) {
            float v0 = hi2(ef0), v1 = hi2(ef1);
            *(float2*)&out_ef[eB * D + f2] = make_float2(v0, v1);
            long rb = (long)row_s[2 * j + 1] * D;
            atomicAdd(&g_agg_h[rb + f2], v0);
            atomicAdd(&g_agg_h[rb + f2 + 1], v1);
        }
    }

    // ---- coord_mlp: cw = silu(edge_feat @ Wc1 + bc1) @ Wc2 ----
    // edge_feat = att * mij, so dot(edge_feat, Wc1col) = att * dot(mij, Wc1col)
#pragma unroll
    for (int j = 0; j < 8; j++) { a0[j] = 0ull; a1[j] = 0ull; }
    mm2<128>(in_t, Wc1, f2, a0, a1);
    {
        float2 bc = *(const float2*)&bc1[f2];
        float2 wc = *(const float2*)&Wc2[f2];
#pragma unroll
        for (int j = 0; j < 8; j++) {
            float d00 = lo2(a0[j]), d01 = hi2(a0[j]);   // feature f2, edges A/B
            float d10 = lo2(a1[j]), d11 = hi2(a1[j]);   // feature f2+1
            float aA = att_s[2 * j], aB = att_s[2 * j + 1];
            float s0 = siluf(fmaf(aA, d00, bc.x)) * wc.x + siluf(fmaf(aA, d10, bc.y)) * wc.y;
            float s1 = siluf(fmaf(aB, d01, bc.x)) * wc.x + siluf(fmaf(aB, d11, bc.y)) * wc.y;
            float r0 = wsum(s0);
            float r1 = wsum(s1);
            if (lane == 0) { red_s[warp][2 * j] = r0; red_s[warp][2 * j + 1] = r1; }
        }
    }
    __syncthreads();
    if (t < EPB)
        cw_s[t] = red_s[0][t] + red_s[1][t];
    __syncthreads();

    // ---- trans = clip(coord_diff * cw, +/-10); scatter into agg_c, cnt ----
    if (t < EPB * 3) {
        int e = t / 3, d = t % 3;
        long eg = e0 + e;
        if (eg < E) {
            float tr = cd_s[e][d] * cw_s[e];
            tr = fminf(10.0f, fmaxf(-10.0f, tr));
            atomicAdd(&g_agg_c[(long)row_s[e] * 3 + d], tr);
        }
    }
    if (t < EPB) {
        long eg = e0 + t;
        if (eg < E) atomicAdd(&g_cnt[row_s[t]], 1.0f);
    }
}

// ---------------- node kernel: h_out = h + node_mlp([h, agg]) ----------------
// Same aliasing: rows 0-127 h (kept for residual), rows 128-255 agg -> hid.
__global__ __launch_bounds__(64, 10) void node_kernel(
    const float* __restrict__ h,
    const float* __restrict__ Wn1, const float* __restrict__ bn1,
    const float* __restrict__ Wn2, const float* __restrict__ bn2,
    float* __restrict__ h_out, int N)
{
    __shared__ __align__(16) float in_t[256][RS];

    const int t = threadIdx.x;     // 0..63
    const int f2 = 2 * t;
    const long n0 = (long)blockIdx.x * EPB;

#pragma unroll
    for (int e = 0; e < EPB; e++) {
        long n = n0 + e;
        if (n >= N) n = N - 1;
        long nb = n * D;
        in_t[t][e]        = h[nb + t];
        in_t[t + 64][e]   = h[nb + t + 64];
        in_t[128 + t][e]  = g_agg_h[nb + t];
        in_t[192 + t][e]  = g_agg_h[nb + t + 64];
    }
    __syncthreads();

    ull a0[8], a1[8];
#pragma unroll
    for (int j = 0; j < 8; j++) { a0[j] = 0ull; a1[j] = 0ull; }
    mm2<256>(in_t, Wn1, f2, a0, a1);
    __syncthreads();   // reads done; rows 128-255 become hid storage
    {
        float2 b = *(const float2*)&bn1[f2];
        ull b0 = dup2(b.x), b1 = dup2(b.y);
#pragma unroll
        for (int j = 0; j < 8; j++) {
            ADD2(a0[j], a0[j], b0); st2(&in_t[128 + f2][2 * j], silu2(a0[j]));
            ADD2(a1[j], a1[j], b1); st2(&in_t[129 + f2][2 * j], silu2(a1[j]));
        }
    }
    __syncthreads();

#pragma unroll
    for (int j = 0; j < 8; j++) { a0[j] = 0ull; a1[j] = 0ull; }
    mm2<128>((const float (*)[RS])(in_t + 128), Wn2, f2, a0, a1);
    {
        float2 b = *(const float2*)&bn2[f2];
#pragma unroll
        for (int j = 0; j < 8; j++) {
            float2 hA = *(const float2*)&in_t[f2][2 * j];       // h[eA..eB] feature f2
            float2 hB = *(const float2*)&in_t[f2 + 1][2 * j];   // feature f2+1
            long nA = n0 + 2 * j, nB = nA + 1;
            if (nA < N)
                *(float2*)&h_out[nA * D + f2] =
                    make_float2(hA.x + lo2(a0[j]) + b.x, hB.x + lo2(a1[j]) + b.y);
            if (nB < N)
                *(float2*)&h_out[nB * D + f2] =
                    make_float2(hA.y + hi2(a0[j]) + b.x, hB.y + hi2(a1[j]) + b.y);
        }
    }
}

// ---------------- coord finalize: coord + clip(agg_c / max(cnt,1), +/-10) ----
__global__ void coord_kernel(const float* __restrict__ coord,
                             float* __restrict__ coord_out, int N)
{
    int i = blockIdx.x * blockDim.x + threadIdx.x;
    if (i < N * 3) {
        int n = i / 3;
        float m = g_agg_c[i] / fmaxf(g_cnt[n], 1.0f);
        m = fminf(10.0f, fmaxf(-10.0f, m));
        coord_out[i] = coord[i] + m;
    }
}

// ---------------- launch ----------------
extern "C" void kernel_launch(void* const* d_in, const int* in_sizes, int n_in,
                              void* d_out, int out_size)
{
    const float* h     = (const float*)d_in[0];
    const void*  ei    = d_in[1];
    const float* coord = (const float*)d_in[2];
    const float* We1   = (const float*)d_in[3];
    const float* be1   = (const float*)d_in[4];
    const float* We2   = (const float*)d_in[5];
    const float* be2   = (const float*)d_in[6];
    const float* Watt  = (const float*)d_in[7];
    const float* batt  = (const float*)d_in[8];
    const float* Wc1   = (const float*)d_in[9];
    const float* bc1   = (const float*)d_in[10];
    const float* Wc2   = (const float*)d_in[11];
    const float* Wn1   = (const float*)d_in[12];
    const float* bn1   = (const float*)d_in[13];
    const float* Wn2   = (const float*)d_in[14];
    const float* bn2   = (const float*)d_in[15];

    const int N = in_sizes[0] / D;
    const int E = in_sizes[1] / 2;

    float* out       = (float*)d_out;
    float* h_out     = out;
    float* coord_out = out + (long)N * D;
    float* out_ef    = out + (long)N * D + (long)N * 3;

    detect_kernel<<<1, 32>>>((const int*)ei);
    zero_kernel<<<1024, 256>>>(N);

    int eb = (E + EPB - 1) / EPB;
    edge_kernel<<<eb, 64>>>(h, ei, coord,
                            We1, be1, We2, be2, Watt, batt,
                            Wc1, bc1, Wc2, out_ef, E);

    int nb = (N + EPB - 1) / EPB;
    node_kernel<<<nb, 64>>>(h, Wn1, bn1, Wn2, bn2, h_out, N);

    coord_kernel<<<(N * 3 + 255) / 256, 256>>>(coord, coord_out, N);
}